// round 1
// baseline (speedup 1.0000x reference)
#include <cuda_runtime.h>
#include <math.h>

// Problem constants
#define NG_GRAPHS 256
#define NPG 62
#define LROW 800
#define C0 160          // conv output width (L/5)
#define TPB 256

// Shared-memory layout (in floats). bufX padded to 64 rows for guard-free tiles.
constexpr int SM_BUFX = 0;                 // 64*160 = 10240
constexpr int SM_BUFY = SM_BUFX + 10240;   // 64*128 = 8192
constexpr int SM_ALS  = SM_BUFY + 8192;    // 256
constexpr int SM_ALD  = SM_ALS + 256;      // 256
constexpr int SM_P    = SM_ALD + 256;      // 2*62*64 = 7936 (row stride 64 -> float4 aligned)
constexpr int SM_MS   = SM_P + 7936;       // 128
constexpr int SM_DS   = SM_MS + 128;       // 128
constexpr int SM_MISC = SM_DS + 128;       // 64 (gm 16 | z1 16 | z2 8)
constexpr int SM_FLOATS = SM_MISC + 64;    // 27200 floats
constexpr size_t SMEM_BYTES = (size_t)SM_FLOATS * sizeof(float);  // 108800 B; x2 blocks = 217.6 KB <= 228 KB/SM

__device__ __forceinline__ float eluf(float v)   { return v > 0.f ? v : expm1f(v); }
__device__ __forceinline__ float lreluf(float v) { return v > 0.f ? v : 0.2f * v; }

// One GAT layer, fully in shared memory. Input: bufX rows [62][K]. Output: bufX rows [62][4*F].
template<int K, int F, bool DO_ELU>
__device__ __forceinline__ void gat_layer(float* sm,
                                          const float* __restrict__ W,
                                          const float* __restrict__ a_s,
                                          const float* __restrict__ a_d,
                                          const float* __restrict__ b)
{
    constexpr int C  = 4 * F;
    constexpr int CG = C / 4;     // col groups of 4
    constexpr int FG = F / 4;     // per-head col groups of 4

    float* bufX = sm + SM_BUFX;
    float* bufY = sm + SM_BUFY;
    float* als  = sm + SM_ALS;
    float* ald  = sm + SM_ALD;
    float* P    = sm + SM_P;
    float* ms   = sm + SM_MS;
    float* ds   = sm + SM_DS;
    const int tid = threadIdx.x;

    // ---- 1) Linear: bufY[n][c] = sum_k bufX[n][k] * W[k][c] ----
    // 4-node x 4-col register tiles; W rows hit L1 (reused 62x per block),
    // activations are smem broadcasts across the warp.
    for (int tile = tid; tile < 16 * CG; tile += TPB) {
        const int cg = tile % CG;
        const int ng = tile / CG;
        const int n0 = ng * 4;
        const int c0 = cg * 4;
        float acc[4][4];
        #pragma unroll
        for (int n = 0; n < 4; n++)
            #pragma unroll
            for (int c = 0; c < 4; c++) acc[n][c] = 0.f;

        const float* Wp = W + c0;
        const float* xp = bufX + n0 * K;
        #pragma unroll 4
        for (int k = 0; k < K; ++k) {
            const float4 w = *reinterpret_cast<const float4*>(Wp + k * C);
            float a[4];
            #pragma unroll
            for (int n = 0; n < 4; n++) a[n] = xp[n * K + k];
            #pragma unroll
            for (int n = 0; n < 4; n++) {
                acc[n][0] = fmaf(a[n], w.x, acc[n][0]);
                acc[n][1] = fmaf(a[n], w.y, acc[n][1]);
                acc[n][2] = fmaf(a[n], w.z, acc[n][2]);
                acc[n][3] = fmaf(a[n], w.w, acc[n][3]);
            }
        }
        #pragma unroll
        for (int n = 0; n < 4; n++) {
            if (n0 + n < NPG) {
                float4 v = make_float4(acc[n][0], acc[n][1], acc[n][2], acc[n][3]);
                *reinterpret_cast<float4*>(bufY + (n0 + n) * C + c0) = v;
            }
        }
    }
    __syncthreads();

    // ---- 2) Attention logits: als[n][h], ald[n][h] ----
    for (int t = tid; t < 2 * NPG * 4; t += TPB) {
        const int which = (t >= NPG * 4) ? 1 : 0;
        const int r = which ? (t - NPG * 4) : t;
        const int n = r >> 2;
        const int h = r & 3;
        const float* av = (which ? a_d : a_s) + h * F;
        const float* yp = bufY + n * C + h * F;
        float s = 0.f;
        #pragma unroll
        for (int f = 0; f < F; f++) s = fmaf(yp[f], av[f], s);
        (which ? ald : als)[r] = s;
    }
    __syncthreads();

    // ---- 3) Per-head attention (2 heads per pass) + aggregation ----
    for (int h0 = 0; h0 < 4; h0 += 2) {
        // softmax stats per destination node j
        if (tid < 2 * NPG) {
            const int j  = tid % NPG;
            const int hh = tid / NPG;
            const int h  = h0 + hh;
            const float dj = ald[j * 4 + h];
            float m = -1e30f, den = 0.f;
            for (int i = 0; i < NPG; i++) {
                const float e = lreluf(als[i * 4 + h] + dj);
                if (e > m) { den = den * __expf(m - e) + 1.f; m = e; }
                else       { den += __expf(e - m); }
            }
            ms[hh * 64 + j] = m;
            ds[hh * 64 + j] = 1.f / den;
        }
        __syncthreads();

        // alpha matrix P[hh][i][j] (j padded to 64)
        for (int t = tid; t < 2 * NPG * 64; t += TPB) {
            const int hh = t / (NPG * 64);
            const int r  = t % (NPG * 64);
            const int i  = r >> 6;
            const int j  = r & 63;
            float v = 0.f;
            if (j < NPG) {
                const int h = h0 + hh;
                const float e = lreluf(als[i * 4 + h] + ald[j * 4 + h]);
                v = __expf(e - ms[hh * 64 + j]) * ds[hh * 64 + j];
            }
            P[t] = v;
        }
        __syncthreads();

        // out[j][h*F+f] = sum_i P[hh][i][j] * bufY[i][h*F+f]  (4j x 4f tiles)
        for (int tile = tid; tile < 2 * 16 * FG; tile += TPB) {
            const int fg   = tile % FG;
            const int rest = tile / FG;
            const int jg   = rest % 16;
            const int hh   = rest / 16;
            const int h    = h0 + hh;
            const int j0   = jg * 4;
            const float* Pp = P + hh * NPG * 64 + j0;
            const float* yp = bufY + h * F + fg * 4;
            float acc[4][4];
            #pragma unroll
            for (int a = 0; a < 4; a++)
                #pragma unroll
                for (int c = 0; c < 4; c++) acc[a][c] = 0.f;
            #pragma unroll 2
            for (int i = 0; i < NPG; i++) {
                const float4 p = *reinterpret_cast<const float4*>(Pp + i * 64);
                const float4 y = *reinterpret_cast<const float4*>(yp + i * C);
                acc[0][0] = fmaf(p.x, y.x, acc[0][0]); acc[0][1] = fmaf(p.x, y.y, acc[0][1]);
                acc[0][2] = fmaf(p.x, y.z, acc[0][2]); acc[0][3] = fmaf(p.x, y.w, acc[0][3]);
                acc[1][0] = fmaf(p.y, y.x, acc[1][0]); acc[1][1] = fmaf(p.y, y.y, acc[1][1]);
                acc[1][2] = fmaf(p.y, y.z, acc[1][2]); acc[1][3] = fmaf(p.y, y.w, acc[1][3]);
                acc[2][0] = fmaf(p.z, y.x, acc[2][0]); acc[2][1] = fmaf(p.z, y.y, acc[2][1]);
                acc[2][2] = fmaf(p.z, y.z, acc[2][2]); acc[2][3] = fmaf(p.z, y.w, acc[2][3]);
                acc[3][0] = fmaf(p.w, y.x, acc[3][0]); acc[3][1] = fmaf(p.w, y.y, acc[3][1]);
                acc[3][2] = fmaf(p.w, y.z, acc[3][2]); acc[3][3] = fmaf(p.w, y.w, acc[3][3]);
            }
            const float4 bb = *reinterpret_cast<const float4*>(b + h * F + fg * 4);
            #pragma unroll
            for (int jj = 0; jj < 4; jj++) {
                if (j0 + jj < NPG) {
                    float v0 = acc[jj][0] + bb.x;
                    float v1 = acc[jj][1] + bb.y;
                    float v2 = acc[jj][2] + bb.z;
                    float v3 = acc[jj][3] + bb.w;
                    if (DO_ELU) { v0 = eluf(v0); v1 = eluf(v1); v2 = eluf(v2); v3 = eluf(v3); }
                    *reinterpret_cast<float4*>(bufX + (j0 + jj) * C + h * F + fg * 4)
                        = make_float4(v0, v1, v2, v3);
                }
            }
        }
        __syncthreads();
    }
}

struct KParams {
    const float *x, *mcf_w, *mcf_b;
    const float *W0, *as0, *ad0, *b0;
    const float *W1, *as1, *ad1, *b1;
    const float *W2, *as2, *ad2, *b2;
    const float *W3, *as3, *ad3, *b3;
    const float *Wm1, *bm1, *Wm2, *bm2, *Wm3, *bm3;
    float *out;
};

__global__ void __launch_bounds__(TPB, 2)
eeg_gat_kernel(KParams p)
{
    extern __shared__ float sm[];
    const int g   = blockIdx.x;
    const int tid = threadIdx.x;
    float* bufX = sm + SM_BUFX;

    // ---- Temporal conv (kernel 5, stride 5) + ELU, fused ----
    const float w0 = p.mcf_w[0], w1 = p.mcf_w[1], w2 = p.mcf_w[2],
                w3 = p.mcf_w[3], w4 = p.mcf_w[4];
    const float bc = p.mcf_b[0];
    const float* xg = p.x + (size_t)g * NPG * LROW;
    #pragma unroll 2
    for (int idx = tid; idx < NPG * C0; idx += TPB) {
        const int n = idx / C0;
        const int c = idx % C0;
        const float* xp = xg + n * LROW + c * 5;
        float acc = bc;
        acc = fmaf(xp[0], w0, acc);
        acc = fmaf(xp[1], w1, acc);
        acc = fmaf(xp[2], w2, acc);
        acc = fmaf(xp[3], w3, acc);
        acc = fmaf(xp[4], w4, acc);
        bufX[n * C0 + c] = eluf(acc);
    }
    __syncthreads();

    // ---- 4 GAT layers ----
    gat_layer<160, 32, true >(sm, p.W0, p.as0, p.ad0, p.b0);
    gat_layer<128, 16, true >(sm, p.W1, p.as1, p.ad1, p.b1);
    gat_layer< 64,  8, true >(sm, p.W2, p.as2, p.ad2, p.b2);
    gat_layer< 32,  4, false>(sm, p.W3, p.as3, p.ad3, p.b3);
    // bufX now holds h [62][16], compact stride 16.

    // ---- embeddings (tuple element 1), starts after z (256*4 floats) ----
    float* emb = p.out + (size_t)NG_GRAPHS * 4 + (size_t)g * NPG * 16;
    for (int idx = tid; idx < NPG * 16; idx += TPB) emb[idx] = bufX[idx];

    // ---- global mean pool + MLP head ----
    float* gm = sm + SM_MISC;        // 16
    float* z1 = gm + 16;             // 16
    float* z2 = z1 + 16;             // 8
    if (tid < 16) {
        float s = 0.f;
        for (int n = 0; n < NPG; n++) s += bufX[n * 16 + tid];
        gm[tid] = s * (1.f / (float)NPG);
    }
    __syncthreads();
    if (tid < 16) {
        float s = p.bm1[tid];
        #pragma unroll
        for (int k = 0; k < 16; k++) s = fmaf(gm[k], p.Wm1[k * 16 + tid], s);
        z1[tid] = fmaxf(s, 0.f);
    }
    __syncthreads();
    if (tid < 8) {
        float s = p.bm2[tid];
        #pragma unroll
        for (int k = 0; k < 16; k++) s = fmaf(z1[k], p.Wm2[k * 8 + tid], s);
        z2[tid] = fmaxf(s, 0.f);
    }
    __syncthreads();
    if (tid < 4) {
        float s = p.bm3[tid];
        #pragma unroll
        for (int k = 0; k < 8; k++) s = fmaf(z2[k], p.Wm3[k * 4 + tid], s);
        p.out[g * 4 + tid] = s;
    }
}

extern "C" void kernel_launch(void* const* d_in, const int* in_sizes, int n_in,
                              void* d_out, int out_size)
{
    (void)in_sizes; (void)n_in; (void)out_size;
    KParams p;
    p.x     = (const float*)d_in[0];
    // d_in[1] = edge_index (complete graph per sample; structure hardcoded)
    // d_in[2] = batch (implied by layout)
    p.mcf_w = (const float*)d_in[3];
    p.mcf_b = (const float*)d_in[4];
    p.W0  = (const float*)d_in[5];  p.as0 = (const float*)d_in[6];
    p.ad0 = (const float*)d_in[7];  p.b0  = (const float*)d_in[8];
    p.W1  = (const float*)d_in[9];  p.as1 = (const float*)d_in[10];
    p.ad1 = (const float*)d_in[11]; p.b1  = (const float*)d_in[12];
    p.W2  = (const float*)d_in[13]; p.as2 = (const float*)d_in[14];
    p.ad2 = (const float*)d_in[15]; p.b2  = (const float*)d_in[16];
    p.W3  = (const float*)d_in[17]; p.as3 = (const float*)d_in[18];
    p.ad3 = (const float*)d_in[19]; p.b3  = (const float*)d_in[20];
    p.Wm1 = (const float*)d_in[21]; p.bm1 = (const float*)d_in[22];
    p.Wm2 = (const float*)d_in[23]; p.bm2 = (const float*)d_in[24];
    p.Wm3 = (const float*)d_in[25]; p.bm3 = (const float*)d_in[26];
    p.out = (float*)d_out;

    cudaFuncSetAttribute(eeg_gat_kernel,
                         cudaFuncAttributeMaxDynamicSharedMemorySize,
                         (int)SMEM_BYTES);
    eeg_gat_kernel<<<NG_GRAPHS, TPB, SMEM_BYTES>>>(p);
}

// round 3
// speedup vs baseline: 1.2183x; 1.2183x over previous
#include <cuda_runtime.h>
#include <math.h>

#define TPB 512
#define NPG 62
#define LROW 800
#define C0 160
#define NGRAPH 256

// Shared memory layout (floats)
constexpr int SM_BUFX = 0;                 // 64*160 = 10240
constexpr int SM_BUFY = 10240;             // 64*128 = 8192
constexpr int SM_ALS  = SM_BUFY + 8192;    // 256
constexpr int SM_ALD  = SM_ALS + 256;      // 256
constexpr int SM_P    = SM_ALD + 256;      // 124 rows * 68 = 8432 (pad 8448)
constexpr int SM_MS   = SM_P + 8448;       // 128
constexpr int SM_DS   = SM_MS + 128;       // 128
constexpr int SM_MISC = SM_DS + 128;       // 64
constexpr int SM_FLOATS = SM_MISC + 64;    // 27712 floats = 110848 B
constexpr size_t SMEM_BYTES = (size_t)SM_FLOATS * sizeof(float);  // x2 blocks = 221.7KB/SM

// FMA-pipe exp: magic-number round + 2-term Cody-Waite + degree-5 Horner.
// |rel err| ~ 2e-6 for x <= 0. No MUFU.
__device__ __forceinline__ float fexp(float x) {
    x = fmaxf(x, -80.0f);
    const float t  = fmaf(x, 1.4426950408889634f, 12582912.0f); // 1.5*2^23 magic
    const float fj = t - 12582912.0f;
    float r = fmaf(fj, -0.693359375f, x);          // ln2_hi
    r = fmaf(fj, 2.12194440e-4f, r);               // ln2_lo
    float p = fmaf(r, 8.3333333e-3f, 4.1666666e-2f);   // 1/120, 1/24
    p = fmaf(p, r, 1.6666667e-1f);
    p = fmaf(p, r, 0.5f);
    p = fmaf(p, r, 1.0f);
    p = fmaf(p, r, 1.0f);
    const int sc = ((__float_as_int(t) - 0x4B400000) << 23) + 0x3F800000;
    return p * __int_as_float(sc);
}

__device__ __forceinline__ float eluf(float v)   { return v > 0.f ? v : fexp(v) - 1.0f; }
__device__ __forceinline__ float lreluf(float v) { return v > 0.f ? v : 0.2f * v; }

// Linear: bufY[n][c] = sum_k bufX[n][k] * W[k][c], rows padded to 64 (rows>=62 -> 0)
template<int K, int C, int NT>
__device__ __forceinline__ void linear_layer(const float* __restrict__ W, float* sm)
{
    constexpr int CG = C / 4;
    constexpr int NGRP = 64 / NT;
    const float* bufX = sm + SM_BUFX;
    float* bufY = sm + SM_BUFY;
    for (int tile = threadIdx.x; tile < NGRP * CG; tile += TPB) {
        const int cg = tile % CG;
        const int n0 = (tile / CG) * NT;
        const int c0 = cg * 4;
        float acc[NT][4];
        #pragma unroll
        for (int n = 0; n < NT; n++) { acc[n][0]=0.f; acc[n][1]=0.f; acc[n][2]=0.f; acc[n][3]=0.f; }
        const float* Wp = W + c0;
        #pragma unroll 2
        for (int k0 = 0; k0 < K; k0 += 4) {
            float4 a[NT];
            #pragma unroll
            for (int n = 0; n < NT; n++)
                a[n] = *reinterpret_cast<const float4*>(bufX + (n0 + n) * K + k0);
            #pragma unroll
            for (int kk = 0; kk < 4; kk++) {
                const float4 w = __ldg(reinterpret_cast<const float4*>(Wp + (k0 + kk) * C));
                #pragma unroll
                for (int n = 0; n < NT; n++) {
                    const float av = (kk == 0) ? a[n].x : (kk == 1) ? a[n].y : (kk == 2) ? a[n].z : a[n].w;
                    acc[n][0] = fmaf(av, w.x, acc[n][0]);
                    acc[n][1] = fmaf(av, w.y, acc[n][1]);
                    acc[n][2] = fmaf(av, w.z, acc[n][2]);
                    acc[n][3] = fmaf(av, w.w, acc[n][3]);
                }
            }
        }
        #pragma unroll
        for (int n = 0; n < NT; n++) {
            const int row = n0 + n;
            const float4 v = (row < NPG)
                ? make_float4(acc[n][0], acc[n][1], acc[n][2], acc[n][3])
                : make_float4(0.f, 0.f, 0.f, 0.f);
            *reinterpret_cast<float4*>(bufY + row * C + c0) = v;
        }
    }
}

template<int F>
__device__ __forceinline__ void logits(float* sm, const float* __restrict__ a_s,
                                       const float* __restrict__ a_d)
{
    constexpr int C = 4 * F;
    const float* bufY = sm + SM_BUFY;
    float* als = sm + SM_ALS;
    float* ald = sm + SM_ALD;
    for (int t = threadIdx.x; t < 2 * NPG * 4; t += TPB) {
        const int which = (t >= NPG * 4);
        const int r = which ? t - NPG * 4 : t;
        const int n = r >> 2, h = r & 3;
        const float* av = (which ? a_d : a_s) + h * F;
        const float* yp = bufY + n * C + h * F;
        float s = 0.f;
        #pragma unroll
        for (int f = 0; f < F; f++) s = fmaf(yp[f], __ldg(av + f), s);
        (which ? ald : als)[r] = s;
    }
}

// One 2-head attention pass. P layout: [hh][dst j][src i], row stride 68, i padded to 64.
template<int F, int JT, bool DO_ELU>
__device__ __forceinline__ void attention_pass(float* sm, int h0, const float* __restrict__ b)
{
    constexpr int C  = 4 * F;
    constexpr int FG = F / 4;
    constexpr int JG = (NPG + JT - 1) / JT;
    float* bufX = sm + SM_BUFX;
    const float* bufY = sm + SM_BUFY;
    const float* als = sm + SM_ALS;
    const float* ald = sm + SM_ALD;
    float* P  = sm + SM_P;
    float* ms = sm + SM_MS;
    float* ds = sm + SM_DS;
    const int tid = threadIdx.x;

    // A: raw leaky-relu logits (pad src i>=62 with -1e30)
    for (int t = tid; t < 2 * NPG * 64; t += TPB) {
        const int hh = (t >= NPG * 64);
        const int rem = t - hh * (NPG * 64);
        const int j = rem >> 6, i = rem & 63;
        float e = -1e30f;
        if (i < NPG) {
            const int h = h0 + hh;
            e = lreluf(als[i * 4 + h] + ald[j * 4 + h]);
        }
        P[(hh * NPG + j) * 68 + i] = e;
    }
    __syncthreads();

    // B: per-dst max (4 lanes per row, float4 scans, shfl reduce) — no exp here
    {
        const int c = tid >> 2, sub = tid & 3;
        const int hh = c >> 6, j = c & 63;
        float m = -1e30f;
        if (j < NPG) {
            const float* row = P + (hh * NPG + j) * 68 + sub * 16;
            #pragma unroll
            for (int q = 0; q < 4; q++) {
                const float4 v = *reinterpret_cast<const float4*>(row + q * 4);
                m = fmaxf(m, fmaxf(fmaxf(v.x, v.y), fmaxf(v.z, v.w)));
            }
        }
        m = fmaxf(m, __shfl_xor_sync(0xFFFFFFFFu, m, 1));
        m = fmaxf(m, __shfl_xor_sync(0xFFFFFFFFu, m, 2));
        if (sub == 0 && j < NPG) ms[c] = m;
    }
    __syncthreads();

    // C: single exp pass (FMA-pipe fexp); pad entries -> exact 0
    for (int t = tid; t < 2 * NPG * 64; t += TPB) {
        const int hh = (t >= NPG * 64);
        const int rem = t - hh * (NPG * 64);
        const int j = rem >> 6, i = rem & 63;
        const int idx = (hh * NPG + j) * 68 + i;
        float v = 0.f;
        if (i < NPG) v = fexp(P[idx] - ms[hh * 64 + j]);
        P[idx] = v;
    }
    __syncthreads();

    // D: per-dst sum -> reciprocal (folded into epilogue, NOT into P)
    {
        const int c = tid >> 2, sub = tid & 3;
        const int hh = c >> 6, j = c & 63;
        float s = 0.f;
        if (j < NPG) {
            const float* row = P + (hh * NPG + j) * 68 + sub * 16;
            #pragma unroll
            for (int q = 0; q < 4; q++) {
                const float4 v = *reinterpret_cast<const float4*>(row + q * 4);
                s += (v.x + v.y) + (v.z + v.w);
            }
        }
        s += __shfl_xor_sync(0xFFFFFFFFu, s, 1);
        s += __shfl_xor_sync(0xFFFFFFFFu, s, 2);
        if (sub == 0 && j < NPG) ds[c] = 1.0f / s;
    }
    __syncthreads();

    // E: out[j] = (sum_i P[j][i] * y[i]) * ds[j] + b ; guard-free i loop to 64
    for (int tile = tid; tile < 2 * JG * FG; tile += TPB) {
        const int fg = tile % FG;
        const int rest = tile / FG;
        const int jg = rest % JG;
        const int hh = rest / JG;
        const int h = h0 + hh;
        const int j0 = jg * JT;
        const int c0 = fg * 4;
        float acc[JT][4];
        #pragma unroll
        for (int r = 0; r < JT; r++) { acc[r][0]=0.f; acc[r][1]=0.f; acc[r][2]=0.f; acc[r][3]=0.f; }
        const float* yb = bufY + h * F + c0;
        const float* Pb = P + (hh * NPG + j0) * 68;
        #pragma unroll 2
        for (int i0 = 0; i0 < 64; i0 += 4) {
            float4 pr[JT];
            #pragma unroll
            for (int r = 0; r < JT; r++)
                pr[r] = *reinterpret_cast<const float4*>(Pb + r * 68 + i0);
            #pragma unroll
            for (int ii = 0; ii < 4; ii++) {
                const float4 y = *reinterpret_cast<const float4*>(yb + (i0 + ii) * C);
                #pragma unroll
                for (int r = 0; r < JT; r++) {
                    const float pv = (ii == 0) ? pr[r].x : (ii == 1) ? pr[r].y : (ii == 2) ? pr[r].z : pr[r].w;
                    acc[r][0] = fmaf(pv, y.x, acc[r][0]);
                    acc[r][1] = fmaf(pv, y.y, acc[r][1]);
                    acc[r][2] = fmaf(pv, y.z, acc[r][2]);
                    acc[r][3] = fmaf(pv, y.w, acc[r][3]);
                }
            }
        }
        const float4 bb = __ldg(reinterpret_cast<const float4*>(b + h * F + c0));
        #pragma unroll
        for (int r = 0; r < JT; r++) {
            const int j = j0 + r;
            if (j < NPG) {
                const float sc = ds[hh * 64 + j];
                float v0 = fmaf(acc[r][0], sc, bb.x);
                float v1 = fmaf(acc[r][1], sc, bb.y);
                float v2 = fmaf(acc[r][2], sc, bb.z);
                float v3 = fmaf(acc[r][3], sc, bb.w);
                if (DO_ELU) { v0 = eluf(v0); v1 = eluf(v1); v2 = eluf(v2); v3 = eluf(v3); }
                *reinterpret_cast<float4*>(bufX + j * C + h * F + c0) = make_float4(v0, v1, v2, v3);
            }
        }
    }
    __syncthreads();
}

struct KParams {
    const float *x, *mcf_w, *mcf_b;
    const float *W0, *as0, *ad0, *b0;
    const float *W1, *as1, *ad1, *b1;
    const float *W2, *as2, *ad2, *b2;
    const float *W3, *as3, *ad3, *b3;
    const float *Wm1, *bm1, *Wm2, *bm2, *Wm3, *bm3;
    float *out;
};

__global__ void __launch_bounds__(TPB, 2)
eeg_gat_kernel(KParams p)
{
    extern __shared__ float sm[];
    const int g   = blockIdx.x;
    const int tid = threadIdx.x;
    float* bufX = sm + SM_BUFX;

    // Temporal conv (kernel 5, stride 5) + ELU
    const float w0 = p.mcf_w[0], w1 = p.mcf_w[1], w2 = p.mcf_w[2],
                w3 = p.mcf_w[3], w4 = p.mcf_w[4];
    const float bc = p.mcf_b[0];
    const float* xg = p.x + (size_t)g * NPG * LROW;
    #pragma unroll 2
    for (int idx = tid; idx < NPG * C0; idx += TPB) {
        const int n = idx / C0;
        const int c = idx % C0;
        const float* xp = xg + n * LROW + c * 5;
        float acc = bc;
        acc = fmaf(xp[0], w0, acc);
        acc = fmaf(xp[1], w1, acc);
        acc = fmaf(xp[2], w2, acc);
        acc = fmaf(xp[3], w3, acc);
        acc = fmaf(xp[4], w4, acc);
        bufX[n * C0 + c] = eluf(acc);
    }
    __syncthreads();

    // Layer 0: 160 -> 4x32
    linear_layer<160, 128, 4>(p.W0, sm); __syncthreads();
    logits<32>(sm, p.as0, p.ad0);        __syncthreads();
    attention_pass<32, 2, true>(sm, 0, p.b0);
    attention_pass<32, 2, true>(sm, 2, p.b0);

    // Layer 1: 128 -> 4x16
    linear_layer<128, 64, 2>(p.W1, sm);  __syncthreads();
    logits<16>(sm, p.as1, p.ad1);        __syncthreads();
    attention_pass<16, 1, true>(sm, 0, p.b1);
    attention_pass<16, 1, true>(sm, 2, p.b1);

    // Layer 2: 64 -> 4x8
    linear_layer<64, 32, 1>(p.W2, sm);   __syncthreads();
    logits<8>(sm, p.as2, p.ad2);         __syncthreads();
    attention_pass<8, 1, true>(sm, 0, p.b2);
    attention_pass<8, 1, true>(sm, 2, p.b2);

    // Layer 3: 32 -> 4x4 (no ELU)
    linear_layer<32, 16, 1>(p.W3, sm);   __syncthreads();
    logits<4>(sm, p.as3, p.ad3);         __syncthreads();
    attention_pass<4, 1, false>(sm, 0, p.b3);
    attention_pass<4, 1, false>(sm, 2, p.b3);
    // bufX: h [62][16]

    // embeddings out (after z block of 256*4)
    float* emb = p.out + (size_t)NGRAPH * 4 + (size_t)g * NPG * 16;
    for (int idx = tid; idx < NPG * 16; idx += TPB) emb[idx] = bufX[idx];

    // mean pool + MLP head
    float* gm = sm + SM_MISC;
    float* z1 = gm + 16;
    float* z2 = z1 + 16;
    if (tid < 16) {
        float s = 0.f;
        for (int n = 0; n < NPG; n++) s += bufX[n * 16 + tid];
        gm[tid] = s * (1.f / (float)NPG);
    }
    __syncthreads();
    if (tid < 16) {
        float s = p.bm1[tid];
        #pragma unroll
        for (int k = 0; k < 16; k++) s = fmaf(gm[k], p.Wm1[k * 16 + tid], s);
        z1[tid] = fmaxf(s, 0.f);
    }
    __syncthreads();
    if (tid < 8) {
        float s = p.bm2[tid];
        #pragma unroll
        for (int k = 0; k < 16; k++) s = fmaf(z1[k], p.Wm2[k * 8 + tid], s);
        z2[tid] = fmaxf(s, 0.f);
    }
    __syncthreads();
    if (tid < 4) {
        float s = p.bm3[tid];
        #pragma unroll
        for (int k = 0; k < 8; k++) s = fmaf(z2[k], p.Wm3[k * 4 + tid], s);
        p.out[g * 4 + tid] = s;
    }
}

extern "C" void kernel_launch(void* const* d_in, const int* in_sizes, int n_in,
                              void* d_out, int out_size)
{
    (void)in_sizes; (void)n_in; (void)out_size;
    KParams p;
    p.x     = (const float*)d_in[0];
    p.mcf_w = (const float*)d_in[3];
    p.mcf_b = (const float*)d_in[4];
    p.W0  = (const float*)d_in[5];  p.as0 = (const float*)d_in[6];
    p.ad0 = (const float*)d_in[7];  p.b0  = (const float*)d_in[8];
    p.W1  = (const float*)d_in[9];  p.as1 = (const float*)d_in[10];
    p.ad1 = (const float*)d_in[11]; p.b1  = (const float*)d_in[12];
    p.W2  = (const float*)d_in[13]; p.as2 = (const float*)d_in[14];
    p.ad2 = (const float*)d_in[15]; p.b2  = (const float*)d_in[16];
    p.W3  = (const float*)d_in[17]; p.as3 = (const float*)d_in[18];
    p.ad3 = (const float*)d_in[19]; p.b3  = (const float*)d_in[20];
    p.Wm1 = (const float*)d_in[21]; p.bm1 = (const float*)d_in[22];
    p.Wm2 = (const float*)d_in[23]; p.bm2 = (const float*)d_in[24];
    p.Wm3 = (const float*)d_in[25]; p.bm3 = (const float*)d_in[26];
    p.out = (float*)d_out;

    cudaFuncSetAttribute(eeg_gat_kernel,
                         cudaFuncAttributeMaxDynamicSharedMemorySize,
                         (int)SMEM_BYTES);
    eeg_gat_kernel<<<NGRAPH, TPB, SMEM_BYTES>>>(p);
}

// round 5
// speedup vs baseline: 1.4551x; 1.1944x over previous
#include <cuda_runtime.h>
#include <math.h>

#define TPB 512
#define NPG 62
#define LROW 800
#define C0 160
#define NGRAPH 256

// Shared memory layout (floats)
constexpr int SM_BUFX = 0;                  // 64*160 = 10240
constexpr int SM_BUFY = 10240;              // 64*128 = 8192
constexpr int SM_ALS  = SM_BUFY + 8192;     // 256
constexpr int SM_ALD  = SM_ALS + 256;       // 256
constexpr int SM_P    = SM_ALD + 256;       // 2*64*64 = 8192  (P[hh][src i][dst j], stride 64)
constexpr int SM_PMAX = SM_P + 8192;        // 256  ([sub][hh*64+j])
constexpr int SM_PSUM = SM_PMAX + 256;      // 256
constexpr int SM_MISC = SM_PSUM + 256;      // 64
constexpr int SM_FLOATS = SM_MISC + 64;     // 27712 floats = 110848 B
constexpr size_t SMEM_BYTES = (size_t)SM_FLOATS * sizeof(float);  // x2 blocks/SM = 221.7KB

// FMA-pipe exp (no MUFU): magic-number round + Cody-Waite + deg-5 Horner. rel err ~2e-6, x<=0.
__device__ __forceinline__ float fexp(float x) {
    x = fmaxf(x, -80.0f);
    const float t  = fmaf(x, 1.4426950408889634f, 12582912.0f);
    const float fj = t - 12582912.0f;
    float r = fmaf(fj, -0.693359375f, x);
    r = fmaf(fj, 2.12194440e-4f, r);
    float p = fmaf(r, 8.3333333e-3f, 4.1666666e-2f);
    p = fmaf(p, r, 1.6666667e-1f);
    p = fmaf(p, r, 0.5f);
    p = fmaf(p, r, 1.0f);
    p = fmaf(p, r, 1.0f);
    const int sc = ((__float_as_int(t) - 0x4B400000) << 23) + 0x3F800000;
    return p * __int_as_float(sc);
}

__device__ __forceinline__ float eluf(float v)   { return v > 0.f ? v : fexp(v) - 1.0f; }
__device__ __forceinline__ float lreluf(float v) { return v > 0.f ? v : 0.2f * v; }

// Linear: bufY[n][c] = sum_k bufX[n][k] * W[k][c], rows padded to 64 (rows>=62 -> 0)
template<int K, int C, int NT>
__device__ __forceinline__ void linear_layer(const float* __restrict__ W, float* sm)
{
    constexpr int CG = C / 4;
    constexpr int NGRP = 64 / NT;
    const float* bufX = sm + SM_BUFX;
    float* bufY = sm + SM_BUFY;
    for (int tile = threadIdx.x; tile < NGRP * CG; tile += TPB) {
        const int cg = tile % CG;
        const int n0 = (tile / CG) * NT;
        const int c0 = cg * 4;
        float acc[NT][4];
        #pragma unroll
        for (int n = 0; n < NT; n++) { acc[n][0]=0.f; acc[n][1]=0.f; acc[n][2]=0.f; acc[n][3]=0.f; }
        const float* Wp = W + c0;
        #pragma unroll 2
        for (int k0 = 0; k0 < K; k0 += 4) {
            float4 a[NT];
            #pragma unroll
            for (int n = 0; n < NT; n++)
                a[n] = *reinterpret_cast<const float4*>(bufX + (n0 + n) * K + k0);
            #pragma unroll
            for (int kk = 0; kk < 4; kk++) {
                const float4 w = __ldg(reinterpret_cast<const float4*>(Wp + (k0 + kk) * C));
                #pragma unroll
                for (int n = 0; n < NT; n++) {
                    const float av = (kk == 0) ? a[n].x : (kk == 1) ? a[n].y : (kk == 2) ? a[n].z : a[n].w;
                    acc[n][0] = fmaf(av, w.x, acc[n][0]);
                    acc[n][1] = fmaf(av, w.y, acc[n][1]);
                    acc[n][2] = fmaf(av, w.z, acc[n][2]);
                    acc[n][3] = fmaf(av, w.w, acc[n][3]);
                }
            }
        }
        #pragma unroll
        for (int n = 0; n < NT; n++) {
            const int row = n0 + n;
            const float4 v = (row < NPG)
                ? make_float4(acc[n][0], acc[n][1], acc[n][2], acc[n][3])
                : make_float4(0.f, 0.f, 0.f, 0.f);
            *reinterpret_cast<float4*>(bufY + row * C + c0) = v;
        }
    }
}

template<int F>
__device__ __forceinline__ void logits(float* sm, const float* __restrict__ a_s,
                                       const float* __restrict__ a_d)
{
    constexpr int C = 4 * F;
    const float* bufY = sm + SM_BUFY;
    float* als = sm + SM_ALS;
    float* ald = sm + SM_ALD;
    const int t = threadIdx.x;
    if (t < 2 * NPG * 4) {
        const int which = (t >= NPG * 4);
        const int r = which ? t - NPG * 4 : t;
        const int n = r >> 2, h = r & 3;
        const float* av = (which ? a_d : a_s) + h * F;
        const float* yp = bufY + n * C + h * F;
        float s = 0.f;
        #pragma unroll
        for (int f4 = 0; f4 < F / 4; f4++) {
            const float4 y = *reinterpret_cast<const float4*>(yp + f4 * 4);
            const float4 a = __ldg(reinterpret_cast<const float4*>(av + f4 * 4));
            s = fmaf(y.x, a.x, s); s = fmaf(y.y, a.y, s);
            s = fmaf(y.z, a.z, s); s = fmaf(y.w, a.w, s);
        }
        (which ? ald : als)[r] = s;
    }
}

// 2-head attention pass. P layout: [hh][src i][dst j], row stride 64, i padded to 64 with zeros.
template<int F, int JT, bool DO_ELU>
__device__ __forceinline__ void attention_pass(float* sm, int h0, const float* __restrict__ b)
{
    constexpr int C  = 4 * F;
    constexpr int FG = F / 4;
    constexpr int JG = 64 / JT;
    float* bufX = sm + SM_BUFX;
    const float* bufY = sm + SM_BUFY;
    const float* als = sm + SM_ALS;
    const float* ald = sm + SM_ALD;
    float* P    = sm + SM_P;
    float* pmax = sm + SM_PMAX;
    float* psum = sm + SM_PSUM;
    const int tid = threadIdx.x;

    // ---- Phase A: partial max over src i (2 sub-chunks of 31) ----
    if (tid < 256) {
        const int j = tid & 63;
        const int hh = (tid >> 6) & 1;
        const int sub = tid >> 7;
        if (j < NPG) {
            const int h = h0 + hh;
            const float dj = ald[j * 4 + h];
            float m = -1e30f;
            #pragma unroll 1
            for (int ii = 0; ii < 31; ii++) {
                const int i = sub * 31 + ii;
                m = fmaxf(m, lreluf(als[i * 4 + h] + dj));
            }
            pmax[sub * 128 + hh * 64 + j] = m;
        }
    }
    __syncthreads();

    // ---- Phase B: exp + store P (transposed, stride-1 lanes) + partial sum ----
    if (tid < 256) {
        const int j = tid & 63;
        const int hh = (tid >> 6) & 1;
        const int sub = tid >> 7;
        if (j < NPG) {
            const int h = h0 + hh;
            const float m  = fmaxf(pmax[hh * 64 + j], pmax[128 + hh * 64 + j]);
            const float dj = ald[j * 4 + h] - m;
            float s = 0.f;
            float* Pc = P + hh * 4096 + j;
            #pragma unroll 1
            for (int ii = 0; ii < 31; ii++) {
                const int i = sub * 31 + ii;
                const float v = fexp(lreluf(als[i * 4 + h] + (dj + m)) - m);
                Pc[i * 64] = v;
                s += v;
            }
            psum[sub * 128 + hh * 64 + j] = s;
            Pc[(62 + sub) * 64] = 0.f;   // zero pad rows 62,63
        }
    }
    __syncthreads();

    // ---- Phase E: out[j][c] = (sum_i P[i][j] * y[i][c]) / den + b ----
    if (tid < 2 * JG * FG) {
        const int fg = tid % FG;
        const int rest = tid / FG;
        const int jg = rest % JG;
        const int hh = rest / JG;
        const int h = h0 + hh;
        const int j0 = jg * JT;
        const int c0 = fg * 4;
        float acc[JT][4];
        #pragma unroll
        for (int r = 0; r < JT; r++) { acc[r][0]=0.f; acc[r][1]=0.f; acc[r][2]=0.f; acc[r][3]=0.f; }
        const float* Pb = P + hh * 4096 + j0;
        const float* yb = bufY + h * F + c0;
        #pragma unroll 4
        for (int i = 0; i < 64; i++) {
            const float4 y = *reinterpret_cast<const float4*>(yb + i * C);
            if (JT == 2) {
                const float2 pv = *reinterpret_cast<const float2*>(Pb + i * 64);
                acc[0][0] = fmaf(pv.x, y.x, acc[0][0]);
                acc[0][1] = fmaf(pv.x, y.y, acc[0][1]);
                acc[0][2] = fmaf(pv.x, y.z, acc[0][2]);
                acc[0][3] = fmaf(pv.x, y.w, acc[0][3]);
                acc[JT-1][0] = fmaf(pv.y, y.x, acc[JT-1][0]);
                acc[JT-1][1] = fmaf(pv.y, y.y, acc[JT-1][1]);
                acc[JT-1][2] = fmaf(pv.y, y.z, acc[JT-1][2]);
                acc[JT-1][3] = fmaf(pv.y, y.w, acc[JT-1][3]);
            } else {
                const float pv = Pb[i * 64];
                acc[0][0] = fmaf(pv, y.x, acc[0][0]);
                acc[0][1] = fmaf(pv, y.y, acc[0][1]);
                acc[0][2] = fmaf(pv, y.z, acc[0][2]);
                acc[0][3] = fmaf(pv, y.w, acc[0][3]);
            }
        }
        const float4 bb = __ldg(reinterpret_cast<const float4*>(b + h * F + c0));
        #pragma unroll
        for (int r = 0; r < JT; r++) {
            const int j = j0 + r;
            if (j < NPG) {
                const float den = psum[hh * 64 + j] + psum[128 + hh * 64 + j];
                const float sc = 1.0f / den;
                float v0 = fmaf(acc[r][0], sc, bb.x);
                float v1 = fmaf(acc[r][1], sc, bb.y);
                float v2 = fmaf(acc[r][2], sc, bb.z);
                float v3 = fmaf(acc[r][3], sc, bb.w);
                if (DO_ELU) { v0 = eluf(v0); v1 = eluf(v1); v2 = eluf(v2); v3 = eluf(v3); }
                *reinterpret_cast<float4*>(bufX + j * C + h * F + c0) = make_float4(v0, v1, v2, v3);
            }
        }
    }
    __syncthreads();
}

struct KParams {
    const float *x, *mcf_w, *mcf_b;
    const float *W0, *as0, *ad0, *b0;
    const float *W1, *as1, *ad1, *b1;
    const float *W2, *as2, *ad2, *b2;
    const float *W3, *as3, *ad3, *b3;
    const float *Wm1, *bm1, *Wm2, *bm2, *Wm3, *bm3;
    float *out;
};

__global__ void __launch_bounds__(TPB, 2)
eeg_gat_kernel(KParams p)
{
    extern __shared__ float sm[];
    const int g   = blockIdx.x;
    const int tid = threadIdx.x;
    float* bufX = sm + SM_BUFX;

    // Temporal conv (kernel 5, stride 5) + ELU
    const float w0 = p.mcf_w[0], w1 = p.mcf_w[1], w2 = p.mcf_w[2],
                w3 = p.mcf_w[3], w4 = p.mcf_w[4];
    const float bc = p.mcf_b[0];
    const float* xg = p.x + (size_t)g * NPG * LROW;
    #pragma unroll 2
    for (int idx = tid; idx < NPG * C0; idx += TPB) {
        const int n = idx / C0;
        const int c = idx % C0;
        const float* xp = xg + n * LROW + c * 5;
        float acc = bc;
        acc = fmaf(xp[0], w0, acc);
        acc = fmaf(xp[1], w1, acc);
        acc = fmaf(xp[2], w2, acc);
        acc = fmaf(xp[3], w3, acc);
        acc = fmaf(xp[4], w4, acc);
        bufX[n * C0 + c] = eluf(acc);
    }
    __syncthreads();

    // Layer 0: 160 -> 4x32
    linear_layer<160, 128, 4>(p.W0, sm); __syncthreads();
    logits<32>(sm, p.as0, p.ad0);        __syncthreads();
    attention_pass<32, 2, true>(sm, 0, p.b0);
    attention_pass<32, 2, true>(sm, 2, p.b0);

    // Layer 1: 128 -> 4x16
    linear_layer<128, 64, 2>(p.W1, sm);  __syncthreads();
    logits<16>(sm, p.as1, p.ad1);        __syncthreads();
    attention_pass<16, 1, true>(sm, 0, p.b1);
    attention_pass<16, 1, true>(sm, 2, p.b1);

    // Layer 2: 64 -> 4x8
    linear_layer<64, 32, 1>(p.W2, sm);   __syncthreads();
    logits<8>(sm, p.as2, p.ad2);         __syncthreads();
    attention_pass<8, 1, true>(sm, 0, p.b2);
    attention_pass<8, 1, true>(sm, 2, p.b2);

    // Layer 3: 32 -> 4x4 (no ELU)
    linear_layer<32, 16, 1>(p.W3, sm);   __syncthreads();
    logits<4>(sm, p.as3, p.ad3);         __syncthreads();
    attention_pass<4, 1, false>(sm, 0, p.b3);
    attention_pass<4, 1, false>(sm, 2, p.b3);
    // bufX: h [62][16]

    // embeddings out (after z block of 256*4)
    float* emb = p.out + (size_t)NGRAPH * 4 + (size_t)g * NPG * 16;
    for (int idx = tid; idx < NPG * 16; idx += TPB) emb[idx] = bufX[idx];

    // mean pool + MLP head
    float* gm = sm + SM_MISC;
    float* z1 = gm + 16;
    float* z2 = z1 + 16;
    if (tid < 16) {
        float s = 0.f;
        for (int n = 0; n < NPG; n++) s += bufX[n * 16 + tid];
        gm[tid] = s * (1.f / (float)NPG);
    }
    __syncthreads();
    if (tid < 16) {
        float s = p.bm1[tid];
        #pragma unroll
        for (int k = 0; k < 16; k++) s = fmaf(gm[k], p.Wm1[k * 16 + tid], s);
        z1[tid] = fmaxf(s, 0.f);
    }
    __syncthreads();
    if (tid < 8) {
        float s = p.bm2[tid];
        #pragma unroll
        for (int k = 0; k < 16; k++) s = fmaf(z1[k], p.Wm2[k * 8 + tid], s);
        z2[tid] = fmaxf(s, 0.f);
    }
    __syncthreads();
    if (tid < 4) {
        float s = p.bm3[tid];
        #pragma unroll
        for (int k = 0; k < 8; k++) s = fmaf(z2[k], p.Wm3[k * 4 + tid], s);
        p.out[g * 4 + tid] = s;
    }
}

extern "C" void kernel_launch(void* const* d_in, const int* in_sizes, int n_in,
                              void* d_out, int out_size)
{
    (void)in_sizes; (void)n_in; (void)out_size;
    KParams p;
    p.x     = (const float*)d_in[0];
    p.mcf_w = (const float*)d_in[3];
    p.mcf_b = (const float*)d_in[4];
    p.W0  = (const float*)d_in[5];  p.as0 = (const float*)d_in[6];
    p.ad0 = (const float*)d_in[7];  p.b0  = (const float*)d_in[8];
    p.W1  = (const float*)d_in[9];  p.as1 = (const float*)d_in[10];
    p.ad1 = (const float*)d_in[11]; p.b1  = (const float*)d_in[12];
    p.W2  = (const float*)d_in[13]; p.as2 = (const float*)d_in[14];
    p.ad2 = (const float*)d_in[15]; p.b2  = (const float*)d_in[16];
    p.W3  = (const float*)d_in[17]; p.as3 = (const float*)d_in[18];
    p.ad3 = (const float*)d_in[19]; p.b3  = (const float*)d_in[20];
    p.Wm1 = (const float*)d_in[21]; p.bm1 = (const float*)d_in[22];
    p.Wm2 = (const float*)d_in[23]; p.bm2 = (const float*)d_in[24];
    p.Wm3 = (const float*)d_in[25]; p.bm3 = (const float*)d_in[26];
    p.out = (float*)d_out;

    cudaFuncSetAttribute(eeg_gat_kernel,
                         cudaFuncAttributeMaxDynamicSharedMemorySize,
                         (int)SMEM_BYTES);
    eeg_gat_kernel<<<NGRAPH, TPB, SMEM_BYTES>>>(p);
}